// round 13
// baseline (speedup 1.0000x reference)
#include <cuda_runtime.h>
#include <cuda_fp16.h>
#include <math.h>

#define Nn 4096
#define Dd 256
#define Kk 2048
#define MAXD 128
#define EPSc 1e-5f

// ---------------- scratch (device globals; no allocation) ----------------
__device__ float  d_HN[Nn * Dd];        // normalized h (fp32, score path)
__device__ __half d_SH[Nn * Dd];        // SC[j] * HN[j] in fp16 (GEMM B matrix)
__device__ float  d_psum[64 * Dd];
__device__ float  d_psq[64 * Dd];
__device__ float  d_mu[Dd];
__device__ float  d_inv[Dd];
__device__ int    d_nbr[Nn * MAXD];
__device__ int    d_ncnt[Nn];
__device__ float  d_deg[Nn];
__device__ float  d_Z1[Nn];
__device__ float  d_Z3[Nn];
__device__ float  d_PF[Nn];
__device__ float  d_SC[Nn];
__device__ int    d_idx[Kk];
__device__ unsigned d_selw[Nn / 32];
__device__ unsigned d_bm[Kk * (Nn / 32)];   // A_hat as bitmaps (1 MB)
__device__ float  d_rinv[Kk];

// ---------------- K1: column stats ----------------
__global__ void k_colstats(const float* __restrict__ h) {
    int b = blockIdx.x, d = threadIdx.x;
    float s = 0.f, q = 0.f;
    int r0 = b * 64;
    for (int r = 0; r < 64; r++) {
        float v = h[(r0 + r) * Dd + d];
        s += v; q += v * v;
    }
    d_psum[b * Dd + d] = s;
    d_psq [b * Dd + d] = q;
}

__global__ void k_colfin(const float* __restrict__ gamma) {
    int d = threadIdx.x;
    float s = 0.f, q = 0.f;
    for (int b = 0; b < 64; b++) { s += d_psum[b * Dd + d]; q += d_psq[b * Dd + d]; }
    float mu  = s / (float)Nn;
    float var = q / (float)Nn - mu * mu;
    d_mu[d]  = mu;
    d_inv[d] = gamma[d] / sqrtf(var + EPSc);
}

// ---------------- K2: normalize h ----------------
__global__ void k_norm(const float* __restrict__ h, const float* __restrict__ beta) {
    int t = blockIdx.x * blockDim.x + threadIdx.x;
    int d4 = t & (Dd / 4 - 1);
    float4 hv = ((const float4*)h)[t];
    float4 mu = ((const float4*)d_mu)[d4];
    float4 iv = ((const float4*)d_inv)[d4];
    float4 be = ((const float4*)beta)[d4];
    float4 o;
    o.x = (hv.x - mu.x) * iv.x + be.x;
    o.y = (hv.y - mu.y) * iv.y + be.y;
    o.z = (hv.z - mu.z) * iv.z + be.z;
    o.w = (hv.w - mu.w) * iv.w + be.w;
    ((float4*)d_HN)[t] = o;
}

// ---------------- K3: CSR from dense binary g ----------------
__global__ void k_csr(const float* __restrict__ g) {
    int row  = (blockIdx.x * blockDim.x + threadIdx.x) >> 5;
    int lane = threadIdx.x & 31;
    if (row >= Nn) return;
    const float4* r4 = (const float4*)(g + (size_t)row * Nn);
    int cnt = 0;
    for (int b = 0; b < 8; b++) {
        float4 v0 = r4[(b * 4 + 0) * 32 + lane];
        float4 v1 = r4[(b * 4 + 1) * 32 + lane];
        float4 v2 = r4[(b * 4 + 2) * 32 + lane];
        float4 v3 = r4[(b * 4 + 3) * 32 + lane];
        unsigned msk = 0u;
        msk |= (v0.x != 0.f) ? 0x0001u : 0u;  msk |= (v0.y != 0.f) ? 0x0002u : 0u;
        msk |= (v0.z != 0.f) ? 0x0004u : 0u;  msk |= (v0.w != 0.f) ? 0x0008u : 0u;
        msk |= (v1.x != 0.f) ? 0x0010u : 0u;  msk |= (v1.y != 0.f) ? 0x0020u : 0u;
        msk |= (v1.z != 0.f) ? 0x0040u : 0u;  msk |= (v1.w != 0.f) ? 0x0080u : 0u;
        msk |= (v2.x != 0.f) ? 0x0100u : 0u;  msk |= (v2.y != 0.f) ? 0x0200u : 0u;
        msk |= (v2.z != 0.f) ? 0x0400u : 0u;  msk |= (v2.w != 0.f) ? 0x0800u : 0u;
        msk |= (v3.x != 0.f) ? 0x1000u : 0u;  msk |= (v3.y != 0.f) ? 0x2000u : 0u;
        msk |= (v3.z != 0.f) ? 0x4000u : 0u;  msk |= (v3.w != 0.f) ? 0x8000u : 0u;
        int lc = __popc(msk);
        int inc = lc;
        #pragma unroll
        for (int o = 1; o < 32; o <<= 1) {
            int n = __shfl_up_sync(0xffffffffu, inc, o);
            if (lane >= o) inc += n;
        }
        int total = __shfl_sync(0xffffffffu, inc, 31);
        int base = cnt + inc - lc;
        while (msk) {
            int q = __ffs((int)msk) - 1;
            msk &= msk - 1;
            int col = (b * 4 + (q >> 2)) * 128 + lane * 4 + (q & 3);
            if (base < MAXD) d_nbr[row * MAXD + base] = col;
            base++;
        }
        cnt += total;
    }
    if (lane == 0) {
        d_ncnt[row] = cnt < MAXD ? cnt : MAXD;
        d_deg[row]  = (float)cnt;
    }
}

// ---------------- K4: per-row agg, Z1, Z3, pf ----------------
__global__ void k_rowfeat(const float* __restrict__ wproj, const float* __restrict__ bproj) {
    int i = blockIdx.x, d = threadIdx.x;
    __shared__ int   snb[MAXD];
    __shared__ float wr[8][3];
    int cnt = d_ncnt[i];
    if (d < cnt) snb[d] = d_nbr[i * MAXD + d];
    __syncthreads();
    float acc = 0.f;
    for (int e = 0; e < cnt; e++) acc += d_HN[snb[e] * Dd + d];
    float agg = acc / d_deg[i];
    float hv  = d_HN[i * Dd + d];
    float w   = wproj[d];
    float a = fabsf(hv - agg), b = agg * w, c = hv * w;
    for (int o = 16; o; o >>= 1) {
        a += __shfl_down_sync(0xffffffffu, a, o);
        b += __shfl_down_sync(0xffffffffu, b, o);
        c += __shfl_down_sync(0xffffffffu, c, o);
    }
    if ((d & 31) == 0) { wr[d >> 5][0] = a; wr[d >> 5][1] = b; wr[d >> 5][2] = c; }
    __syncthreads();
    if (d == 0) {
        float A = 0.f, B = 0.f, C = 0.f;
        for (int k = 0; k < 8; k++) { A += wr[k][0]; B += wr[k][1]; C += wr[k][2]; }
        float bb = bproj[0];
        d_Z1[i] = A;
        d_Z3[i] = B + bb;
        d_PF[i] = 1.f / (1.f + expf(-(C + bb)));
    }
}

// ---------------- K5: fused softmax + scores + top-k bitonic ----------------
__global__ void k_topk(const float* __restrict__ sigma1, float* __restrict__ out_idx) {
    __shared__ unsigned long long sk[Nn];
    __shared__ float sh[1024];
    int t = threadIdx.x;

    float mx = -3.4e38f;
    for (int i = t; i < Nn; i += 1024) mx = fmaxf(mx, d_Z3[i]);
    sh[t] = mx; __syncthreads();
    for (int s = 512; s > 0; s >>= 1) { if (t < s) sh[t] = fmaxf(sh[t], sh[t + s]); __syncthreads(); }
    float M = sh[0]; __syncthreads();
    float sm = 0.f;
    for (int i = t; i < Nn; i += 1024) sm += expf(d_Z3[i] - M);
    sh[t] = sm; __syncthreads();
    for (int s = 512; s > 0; s >>= 1) { if (t < s) sh[t] += sh[t + s]; __syncthreads(); }
    float S = sh[0];
    float s1 = sigma1[0];

    for (int i = t; i < Nn; i += 1024) {
        float pg = expf(d_Z3[i] - M) / S;
        float pl = 1.f / (1.f + expf(-(d_Z1[i] + d_deg[i])));
        float pt = 1.f / (1.f + expf(-(pl + pg)));
        float sc = s1 * pt + (1.f - s1) * d_PF[i];
        d_SC[i] = sc;
        unsigned u = __float_as_uint(sc);
        u = (u & 0x80000000u) ? ~u : (u | 0x80000000u);
        sk[i] = ((unsigned long long)(~u) << 32) | (unsigned)i;
    }
    if (t < Nn / 32) d_selw[t] = 0u;
    __syncthreads();

    for (int k = 2; k <= Nn; k <<= 1) {
        for (int j = k >> 1; j > 0; j >>= 1) {
            #pragma unroll
            for (int p = 0; p < 4; p++) {
                int i = t + p * 1024;
                int ixj = i ^ j;
                if (ixj > i) {
                    bool up = ((i & k) == 0);
                    unsigned long long a = sk[i], b = sk[ixj];
                    if ((a > b) == up) { sk[i] = b; sk[ixj] = a; }
                }
            }
            if (j >= 32) __syncthreads(); else __syncwarp();
        }
    }
    __syncthreads();
    for (int c = t; c < Kk; c += 1024) {
        int j = (int)(sk[c] & 0xffffffffULL);
        d_idx[c] = j;
        atomicOr(&d_selw[j >> 5], 1u << (j & 31));
        out_idx[c] = (float)j;
    }
}

// ---------------- K6a: SH = SC * HN in fp16 (GEMM B matrix) ----------------
__global__ void k_sh() {
    int t = blockIdx.x * blockDim.x + threadIdx.x;      // Nn*Dd/4
    float4 v = ((const float4*)d_HN)[t];
    float s = d_SC[t >> 6];
    __half2 p0 = __floats2half2_rn(s * v.x, s * v.y);
    __half2 p1 = __floats2half2_rn(s * v.z, s * v.w);
    ((__half2*)d_SH)[t * 2 + 0] = p0;
    ((__half2*)d_SH)[t * 2 + 1] = p1;
}

// ---------------- K6b: per-selected-row two-hop bitmap + rinv (no gather) ----------------
__global__ void k_pool() {
    __shared__ unsigned bm[Nn / 32];
    __shared__ int redi[256];
    int r = blockIdx.x, d = threadIdx.x;
    int i = d_idx[r];
    if (d < Nn / 32) bm[d] = 0u;
    __syncthreads();
    int c1 = d_ncnt[i];
    for (int e = d; e < c1; e += 256) {
        int k = d_nbr[i * MAXD + e];
        int c2 = d_ncnt[k];
        const int* nb = &d_nbr[k * MAXD];
        for (int f = 0; f < c2; f++) {
            int j = nb[f];
            atomicOr(&bm[j >> 5], 1u << (j & 31));
        }
    }
    __syncthreads();
    int csel = 0;
    if (d < Nn / 32) {
        unsigned w = bm[d];
        d_bm[r * (Nn / 32) + d] = w;
        csel = __popc(w & d_selw[d]);
    }
    redi[d] = csel;
    __syncthreads();
    for (int s = 128; s > 0; s >>= 1) { if (d < s) redi[d] += redi[d + s]; __syncthreads(); }
    if (d == 0) d_rinv[r] = 1.f / (float)redi[0];
}

// ---------------- K6c: new_h = A_hat @ SH via mma.sync (A bits from bitmap) -------------
// Block tile: M=64 rows, N=64 cols; 8 warps = 4 m-strips x 2 n-halves.
__global__ __launch_bounds__(256) void k_gemm(float* __restrict__ out_newh) {
    __shared__ unsigned sbm[64][Nn / 32];    // 32 KB: block's 64 bitmap rows
    __shared__ __half   sB[64][72];          // 9 KB: B chunk [k=64][n=64] (+pad)
    int tid = threadIdx.x;
    int r0 = blockIdx.x * 64;
    int c0 = blockIdx.y * 64;

    {
        const uint4* src = (const uint4*)&d_bm[(size_t)r0 * (Nn / 32)];
        uint4* dst = (uint4*)&sbm[0][0];
        for (int i = tid; i < 64 * (Nn / 32) / 4; i += 256) dst[i] = src[i];
    }

    int warp = tid >> 5, lane = tid & 31;
    int g = lane >> 2, tg = lane & 3;
    int strip = warp & 3, nhalf = warp >> 2;
    int rowA = strip * 16 + g;
    int rowB = rowA + 8;

    float acc[4][4];
    #pragma unroll
    for (int ns = 0; ns < 4; ns++)
        #pragma unroll
        for (int q = 0; q < 4; q++) acc[ns][q] = 0.f;

    const __half one = __float2half(1.f);
    const __half zer = __float2half(0.f);

    int ldk = tid >> 2;
    int ldn = (tid & 3) * 16;

    for (int kc = 0; kc < Nn / 64; kc++) {
        __syncthreads();
        {
            const uint4* srow = (const uint4*)&d_SH[(size_t)(kc * 64 + ldk) * Dd + c0 + ldn];
            uint4 w0 = srow[0];
            uint4 w1 = srow[1];
            *(uint4*)&sB[ldk][ldn]     = w0;
            *(uint4*)&sB[ldk][ldn + 8] = w1;
        }
        __syncthreads();
        #pragma unroll
        for (int ks = 0; ks < 4; ks++) {
            int k0 = kc * 64 + ks * 16;
            unsigned wA = sbm[rowA][k0 >> 5];
            unsigned wB = sbm[rowB][k0 >> 5];
            int sh = (k0 & 16) + 2 * tg;
            unsigned bA = wA >> sh;
            unsigned bB = wB >> sh;
            __half2 a01 = __halves2half2((bA & 1u) ? one : zer, (bA & 2u) ? one : zer);
            __half2 a23 = __halves2half2((bB & 1u) ? one : zer, (bB & 2u) ? one : zer);
            unsigned bA8 = bA >> 8, bB8 = bB >> 8;
            __half2 a45 = __halves2half2((bA8 & 1u) ? one : zer, (bA8 & 2u) ? one : zer);
            __half2 a67 = __halves2half2((bB8 & 1u) ? one : zer, (bB8 & 2u) ? one : zer);
            unsigned ra0 = *(unsigned*)&a01;
            unsigned ra1 = *(unsigned*)&a23;
            unsigned ra2 = *(unsigned*)&a45;
            unsigned ra3 = *(unsigned*)&a67;
            int kk = ks * 16 + 2 * tg;
            #pragma unroll
            for (int ns = 0; ns < 4; ns++) {
                int n = nhalf * 32 + ns * 8 + g;
                __half b0 = sB[kk][n];
                __half b1 = sB[kk + 1][n];
                __half b2 = sB[kk + 8][n];
                __half b3 = sB[kk + 9][n];
                __half2 bp0 = __halves2half2(b0, b1);
                __half2 bp1 = __halves2half2(b2, b3);
                unsigned rb0 = *(unsigned*)&bp0;
                unsigned rb1 = *(unsigned*)&bp1;
                asm volatile(
                    "mma.sync.aligned.m16n8k16.row.col.f32.f16.f16.f32 "
                    "{%0,%1,%2,%3}, {%4,%5,%6,%7}, {%8,%9}, {%0,%1,%2,%3};"
                    : "+f"(acc[ns][0]), "+f"(acc[ns][1]), "+f"(acc[ns][2]), "+f"(acc[ns][3])
                    : "r"(ra0), "r"(ra1), "r"(ra2), "r"(ra3), "r"(rb0), "r"(rb1));
            }
        }
    }

    #pragma unroll
    for (int ns = 0; ns < 4; ns++) {
        int col = c0 + nhalf * 32 + ns * 8 + 2 * tg;
        int rA = r0 + rowA;
        float2 v0 = make_float2(acc[ns][0], acc[ns][1]);
        float2 v1 = make_float2(acc[ns][2], acc[ns][3]);
        *(float2*)&out_newh[(size_t)rA * Dd + col] = v0;
        *(float2*)&out_newh[(size_t)(rA + 8) * Dd + col] = v1;
    }
}

// ---------------- K7: write g_new directly (membership bit * column rinv) ----------------
__global__ void k_gnew(float* __restrict__ out_gnew) {
    int t = blockIdx.x * blockDim.x + threadIdx.x;
    int r = t >> 11, c = t & (Kk - 1);
    int j = d_idx[c];
    unsigned w = d_bm[r * (Nn / 32) + (j >> 5)];
    out_gnew[t] = ((w >> (j & 31)) & 1u) ? d_rinv[c] : 0.f;
}

// ---------------- launch (single proven fork for csr; all else serial on main) -----------
extern "C" void kernel_launch(void* const* d_in, const int* in_sizes, int n_in,
                              void* d_out, int out_size) {
    const float* g      = (const float*)d_in[0];
    const float* h      = (const float*)d_in[1];
    const float* gamma  = (const float*)d_in[2];
    const float* beta   = (const float*)d_in[3];
    const float* wproj  = (const float*)d_in[4];
    const float* bproj  = (const float*)d_in[5];
    const float* sigma1 = (const float*)d_in[6];

    float* out      = (float*)d_out;
    float* out_gnew = out;                               // Kk*Kk
    float* out_newh = out + (size_t)Kk * Kk;             // Kk*Dd
    float* out_idx  = out_newh + (size_t)Kk * Dd;        // Kk

    static cudaStream_t s1 = nullptr;
    static cudaEvent_t  eFork = nullptr, eJoin = nullptr;
    if (s1 == nullptr) {
        cudaStreamCreateWithFlags(&s1, cudaStreamNonBlocking);
        cudaEventCreateWithFlags(&eFork, cudaEventDisableTiming);
        cudaEventCreateWithFlags(&eJoin, cudaEventDisableTiming);
    }

    cudaEventRecord(eFork, 0);
    cudaStreamWaitEvent(s1, eFork, 0);
    k_csr<<<Nn / 8, 256, 0, s1>>>(g);
    cudaEventRecord(eJoin, s1);

    k_colstats<<<64, 256>>>(h);
    k_colfin  <<<1, 256>>>(gamma);
    k_norm    <<<(Nn * Dd / 4) / 256, 256>>>(h, beta);

    cudaStreamWaitEvent(0, eJoin, 0);
    k_rowfeat <<<Nn, 256>>>(wproj, bproj);
    k_topk    <<<1, 1024>>>(sigma1, out_idx);
    k_sh      <<<(Nn * Dd / 4) / 256, 256>>>();
    k_pool    <<<Kk, 256>>>();
    k_gemm    <<<dim3(Kk / 64, Dd / 64), 256>>>(out_newh);
    k_gnew    <<<(Kk * Kk) / 256, 256>>>(out_gnew);
}

// round 15
// speedup vs baseline: 1.2340x; 1.2340x over previous
#include <cuda_runtime.h>
#include <cuda_fp16.h>
#include <math.h>

#define Nn 4096
#define Dd 256
#define Kk 2048
#define MAXD 128
#define EPSc 1e-5f

// ---------------- scratch (device globals; no allocation) ----------------
__device__ float  d_HN[Nn * Dd];        // normalized h (fp32, score path)
__device__ __half d_HNh[Nn * Dd];       // fp16 mirror (gather path only)
__device__ float  d_psum[64 * Dd];
__device__ float  d_psq[64 * Dd];
__device__ float  d_mu[Dd];
__device__ float  d_inv[Dd];
__device__ int    d_nbr[Nn * MAXD];
__device__ int    d_ncnt[Nn];
__device__ float  d_deg[Nn];
__device__ float  d_Z1[Nn];
__device__ float  d_Z3[Nn];
__device__ float  d_PF[Nn];
__device__ float  d_SC[Nn];
__device__ int    d_idx[Kk];
__device__ unsigned d_selw[Nn / 32];
__device__ unsigned d_bma[Nn * (Nn / 32)];  // two-hop bitmaps for ALL rows (2 MB)
__device__ float  d_rinv[Kk];

// ---------------- K1: column stats ----------------
__global__ void k_colstats(const float* __restrict__ h) {
    int b = blockIdx.x, d = threadIdx.x;
    float s = 0.f, q = 0.f;
    int r0 = b * 64;
    for (int r = 0; r < 64; r++) {
        float v = h[(r0 + r) * Dd + d];
        s += v; q += v * v;
    }
    d_psum[b * Dd + d] = s;
    d_psq [b * Dd + d] = q;
}

__global__ void k_colfin(const float* __restrict__ gamma) {
    int d = threadIdx.x;
    float s = 0.f, q = 0.f;
    for (int b = 0; b < 64; b++) { s += d_psum[b * Dd + d]; q += d_psq[b * Dd + d]; }
    float mu  = s / (float)Nn;
    float var = q / (float)Nn - mu * mu;
    d_mu[d]  = mu;
    d_inv[d] = gamma[d] / sqrtf(var + EPSc);
}

// ---------------- K2: normalize h (float4), fp32 + fp16 mirror ----------------
__global__ void k_norm(const float* __restrict__ h, const float* __restrict__ beta) {
    int t = blockIdx.x * blockDim.x + threadIdx.x;
    int d4 = t & (Dd / 4 - 1);
    float4 hv = ((const float4*)h)[t];
    float4 mu = ((const float4*)d_mu)[d4];
    float4 iv = ((const float4*)d_inv)[d4];
    float4 be = ((const float4*)beta)[d4];
    float4 o;
    o.x = (hv.x - mu.x) * iv.x + be.x;
    o.y = (hv.y - mu.y) * iv.y + be.y;
    o.z = (hv.z - mu.z) * iv.z + be.z;
    o.w = (hv.w - mu.w) * iv.w + be.w;
    ((float4*)d_HN)[t] = o;
    __half2 p0 = __floats2half2_rn(o.x, o.y);
    __half2 p1 = __floats2half2_rn(o.z, o.w);
    ((__half2*)d_HNh)[t * 2 + 0] = p0;
    ((__half2*)d_HNh)[t * 2 + 1] = p1;
}

// ---------------- K3: CSR from dense binary g ----------------
__global__ void k_csr(const float* __restrict__ g) {
    int row  = (blockIdx.x * blockDim.x + threadIdx.x) >> 5;
    int lane = threadIdx.x & 31;
    if (row >= Nn) return;
    const float4* r4 = (const float4*)(g + (size_t)row * Nn);
    int cnt = 0;
    for (int b = 0; b < 8; b++) {
        float4 v0 = r4[(b * 4 + 0) * 32 + lane];
        float4 v1 = r4[(b * 4 + 1) * 32 + lane];
        float4 v2 = r4[(b * 4 + 2) * 32 + lane];
        float4 v3 = r4[(b * 4 + 3) * 32 + lane];
        unsigned msk = 0u;
        msk |= (v0.x != 0.f) ? 0x0001u : 0u;  msk |= (v0.y != 0.f) ? 0x0002u : 0u;
        msk |= (v0.z != 0.f) ? 0x0004u : 0u;  msk |= (v0.w != 0.f) ? 0x0008u : 0u;
        msk |= (v1.x != 0.f) ? 0x0010u : 0u;  msk |= (v1.y != 0.f) ? 0x0020u : 0u;
        msk |= (v1.z != 0.f) ? 0x0040u : 0u;  msk |= (v1.w != 0.f) ? 0x0080u : 0u;
        msk |= (v2.x != 0.f) ? 0x0100u : 0u;  msk |= (v2.y != 0.f) ? 0x0200u : 0u;
        msk |= (v2.z != 0.f) ? 0x0400u : 0u;  msk |= (v2.w != 0.f) ? 0x0800u : 0u;
        msk |= (v3.x != 0.f) ? 0x1000u : 0u;  msk |= (v3.y != 0.f) ? 0x2000u : 0u;
        msk |= (v3.z != 0.f) ? 0x4000u : 0u;  msk |= (v3.w != 0.f) ? 0x8000u : 0u;
        int lc = __popc(msk);
        int inc = lc;
        #pragma unroll
        for (int o = 1; o < 32; o <<= 1) {
            int n = __shfl_up_sync(0xffffffffu, inc, o);
            if (lane >= o) inc += n;
        }
        int total = __shfl_sync(0xffffffffu, inc, 31);
        int base = cnt + inc - lc;
        while (msk) {
            int q = __ffs((int)msk) - 1;
            msk &= msk - 1;
            int col = (b * 4 + (q >> 2)) * 128 + lane * 4 + (q & 3);
            if (base < MAXD) d_nbr[row * MAXD + base] = col;
            base++;
        }
        cnt += total;
    }
    if (lane == 0) {
        d_ncnt[row] = cnt < MAXD ? cnt : MAXD;
        d_deg[row]  = (float)cnt;
    }
}

// ---------------- K3b: two-hop bitmaps for ALL rows (overlapped with topk) --------------
__global__ void k_bma() {
    __shared__ unsigned bm[Nn / 32];
    int i = blockIdx.x, d = threadIdx.x;
    if (d < Nn / 32) bm[d] = 0u;
    __syncthreads();
    int c1 = d_ncnt[i];
    for (int e = d; e < c1; e += 256) {
        int k = d_nbr[i * MAXD + e];
        int c2 = d_ncnt[k];
        const int* nb = &d_nbr[k * MAXD];
        for (int f = 0; f < c2; f++) {
            int j = nb[f];
            atomicOr(&bm[j >> 5], 1u << (j & 31));
        }
    }
    __syncthreads();
    if (d < Nn / 32) d_bma[(size_t)i * (Nn / 32) + d] = bm[d];
}

// ---------------- K4: per-row agg, Z1, Z3, pf ----------------
__global__ void k_rowfeat(const float* __restrict__ wproj, const float* __restrict__ bproj) {
    int i = blockIdx.x, d = threadIdx.x;
    __shared__ int   snb[MAXD];
    __shared__ float wr[8][3];
    int cnt = d_ncnt[i];
    if (d < cnt) snb[d] = d_nbr[i * MAXD + d];
    __syncthreads();
    float acc = 0.f;
    for (int e = 0; e < cnt; e++) acc += d_HN[snb[e] * Dd + d];
    float agg = acc / d_deg[i];
    float hv  = d_HN[i * Dd + d];
    float w   = wproj[d];
    float a = fabsf(hv - agg), b = agg * w, c = hv * w;
    for (int o = 16; o; o >>= 1) {
        a += __shfl_down_sync(0xffffffffu, a, o);
        b += __shfl_down_sync(0xffffffffu, b, o);
        c += __shfl_down_sync(0xffffffffu, c, o);
    }
    if ((d & 31) == 0) { wr[d >> 5][0] = a; wr[d >> 5][1] = b; wr[d >> 5][2] = c; }
    __syncthreads();
    if (d == 0) {
        float A = 0.f, B = 0.f, C = 0.f;
        for (int k = 0; k < 8; k++) { A += wr[k][0]; B += wr[k][1]; C += wr[k][2]; }
        float bb = bproj[0];
        d_Z1[i] = A;
        d_Z3[i] = B + bb;
        d_PF[i] = 1.f / (1.f + expf(-(C + bb)));
    }
}

// ---------------- K5: fused softmax + scores + top-k bitonic ----------------
__global__ void k_topk(const float* __restrict__ sigma1, float* __restrict__ out_idx) {
    __shared__ unsigned long long sk[Nn];
    __shared__ float sh[1024];
    int t = threadIdx.x;

    float mx = -3.4e38f;
    for (int i = t; i < Nn; i += 1024) mx = fmaxf(mx, d_Z3[i]);
    sh[t] = mx; __syncthreads();
    for (int s = 512; s > 0; s >>= 1) { if (t < s) sh[t] = fmaxf(sh[t], sh[t + s]); __syncthreads(); }
    float M = sh[0]; __syncthreads();
    float sm = 0.f;
    for (int i = t; i < Nn; i += 1024) sm += expf(d_Z3[i] - M);
    sh[t] = sm; __syncthreads();
    for (int s = 512; s > 0; s >>= 1) { if (t < s) sh[t] += sh[t + s]; __syncthreads(); }
    float S = sh[0];
    float s1 = sigma1[0];

    for (int i = t; i < Nn; i += 1024) {
        float pg = expf(d_Z3[i] - M) / S;
        float pl = 1.f / (1.f + expf(-(d_Z1[i] + d_deg[i])));
        float pt = 1.f / (1.f + expf(-(pl + pg)));
        float sc = s1 * pt + (1.f - s1) * d_PF[i];
        d_SC[i] = sc;
        unsigned u = __float_as_uint(sc);
        u = (u & 0x80000000u) ? ~u : (u | 0x80000000u);
        sk[i] = ((unsigned long long)(~u) << 32) | (unsigned)i;
    }
    if (t < Nn / 32) d_selw[t] = 0u;
    __syncthreads();

    for (int k = 2; k <= Nn; k <<= 1) {
        for (int j = k >> 1; j > 0; j >>= 1) {
            #pragma unroll
            for (int p = 0; p < 4; p++) {
                int i = t + p * 1024;
                int ixj = i ^ j;
                if (ixj > i) {
                    bool up = ((i & k) == 0);
                    unsigned long long a = sk[i], b = sk[ixj];
                    if ((a > b) == up) { sk[i] = b; sk[ixj] = a; }
                }
            }
            if (j >= 32) __syncthreads(); else __syncwarp();
        }
    }
    __syncthreads();
    for (int c = t; c < Kk; c += 1024) {
        int j = (int)(sk[c] & 0xffffffffULL);
        d_idx[c] = j;
        atomicOr(&d_selw[j >> 5], 1u << (j & 31));
        out_idx[c] = (float)j;
    }
}

// ---------------- K6: gather for selected rows (bitmap preloaded from d_bma) -------------
__global__ void k_gather(float* __restrict__ out_newh) {
    __shared__ unsigned bm[Nn / 32];
    __shared__ int scn[Nn / 32];
    __shared__ int list[Nn];
    __shared__ float red[7][32][8];
    __shared__ int redi[256];
    int r = blockIdx.x, d = threadIdx.x;
    int i = d_idx[r];
    if (d < Nn / 32) bm[d] = d_bma[(size_t)i * (Nn / 32) + d];
    __syncthreads();

    // deterministic ordered extraction via prefix scan over 128 words
    int pc = (d < Nn / 32) ? __popc(bm[d]) : 0;
    if (d < Nn / 32) scn[d] = pc;
    __syncthreads();
    for (int off = 1; off < Nn / 32; off <<= 1) {
        int v = 0;
        if (d < Nn / 32) { v = scn[d]; if (d >= off) v += scn[d - off]; }
        __syncthreads();
        if (d < Nn / 32) scn[d] = v;
        __syncthreads();
    }
    if (d < Nn / 32) {
        int p = scn[d] - pc;
        unsigned v = bm[d];
        while (v) { int b = __ffs((int)v) - 1; v &= v - 1; list[p++] = d * 32 + b; }
    }
    int csel = (d < Nn / 32) ? __popc(bm[d] & d_selw[d]) : 0;
    redi[d] = csel;
    __syncthreads();
    int m = scn[Nn / 32 - 1];
    for (int s = 128; s > 0; s >>= 1) { if (d < s) redi[d] += redi[d + s]; __syncthreads(); }
    if (d == 0) d_rinv[r] = 1.f / (float)redi[0];

    // fp16 gather: 8 groups x 32 lanes, 8 dims/lane, unroll-4
    int grp = d >> 5, l = d & 31;
    const uint4* H4 = (const uint4*)d_HNh;
    float acc0[8], acc1[8];
    #pragma unroll
    for (int q = 0; q < 8; q++) { acc0[q] = 0.f; acc1[q] = 0.f; }
    int e = grp;
    for (; e + 24 < m; e += 32) {
        int j0 = list[e], j1 = list[e + 8], j2 = list[e + 16], j3 = list[e + 24];
        float s0 = d_SC[j0], s1 = d_SC[j1], s2 = d_SC[j2], s3 = d_SC[j3];
        uint4 va = H4[j0 * 32 + l];
        uint4 vb = H4[j1 * 32 + l];
        uint4 vc = H4[j2 * 32 + l];
        uint4 vd = H4[j3 * 32 + l];
        const __half2* ha = (const __half2*)&va;
        const __half2* hb = (const __half2*)&vb;
        const __half2* hc = (const __half2*)&vc;
        const __half2* hd = (const __half2*)&vd;
        #pragma unroll
        for (int q = 0; q < 4; q++) {
            float2 fa = __half22float2(ha[q]);
            float2 fb = __half22float2(hb[q]);
            float2 fc = __half22float2(hc[q]);
            float2 fd = __half22float2(hd[q]);
            acc0[q * 2 + 0] += s0 * fa.x + s2 * fc.x;
            acc0[q * 2 + 1] += s0 * fa.y + s2 * fc.y;
            acc1[q * 2 + 0] += s1 * fb.x + s3 * fd.x;
            acc1[q * 2 + 1] += s1 * fb.y + s3 * fd.y;
        }
    }
    for (; e < m; e += 8) {
        int j = list[e];
        float s = d_SC[j];
        uint4 v = H4[j * 32 + l];
        const __half2* hp = (const __half2*)&v;
        #pragma unroll
        for (int q = 0; q < 4; q++) {
            float2 f = __half22float2(hp[q]);
            acc0[q * 2 + 0] += s * f.x; acc0[q * 2 + 1] += s * f.y;
        }
    }
    #pragma unroll
    for (int q = 0; q < 8; q++) acc0[q] += acc1[q];
    if (grp > 0) {
        #pragma unroll
        for (int q = 0; q < 8; q++) red[grp - 1][l][q] = acc0[q];
    }
    __syncthreads();
    if (grp == 0) {
        #pragma unroll
        for (int gq = 0; gq < 7; gq++)
            #pragma unroll
            for (int q = 0; q < 8; q++) acc0[q] += red[gq][l][q];
        float4 o0 = make_float4(acc0[0], acc0[1], acc0[2], acc0[3]);
        float4 o1 = make_float4(acc0[4], acc0[5], acc0[6], acc0[7]);
        ((float4*)out_newh)[(size_t)r * 64 + l * 2 + 0] = o0;
        ((float4*)out_newh)[(size_t)r * 64 + l * 2 + 1] = o1;
    }
}

// ---------------- K7: g_new from all-rows bitmaps ----------------
__global__ void k_gnew(float* __restrict__ out_gnew) {
    int t = blockIdx.x * blockDim.x + threadIdx.x;
    int r = t >> 11, c = t & (Kk - 1);
    int i = d_idx[r];
    int j = d_idx[c];
    unsigned w = d_bma[(size_t)i * (Nn / 32) + (j >> 5)];
    out_gnew[t] = ((w >> (j & 31)) & 1u) ? d_rinv[c] : 0.f;
}

// ---------------- launch: side chain csr->bma; main h-chain -> scores -> outputs ---------
extern "C" void kernel_launch(void* const* d_in, const int* in_sizes, int n_in,
                              void* d_out, int out_size) {
    const float* g      = (const float*)d_in[0];
    const float* h      = (const float*)d_in[1];
    const float* gamma  = (const float*)d_in[2];
    const float* beta   = (const float*)d_in[3];
    const float* wproj  = (const float*)d_in[4];
    const float* bproj  = (const float*)d_in[5];
    const float* sigma1 = (const float*)d_in[6];

    float* out      = (float*)d_out;
    float* out_gnew = out;                               // Kk*Kk
    float* out_newh = out + (size_t)Kk * Kk;             // Kk*Dd
    float* out_idx  = out_newh + (size_t)Kk * Dd;        // Kk

    static cudaStream_t s1 = nullptr;
    static cudaEvent_t  eFork = nullptr, eCsr = nullptr, eBm = nullptr;
    if (s1 == nullptr) {
        cudaStreamCreateWithFlags(&s1, cudaStreamNonBlocking);
        cudaEventCreateWithFlags(&eFork, cudaEventDisableTiming);
        cudaEventCreateWithFlags(&eCsr, cudaEventDisableTiming);
        cudaEventCreateWithFlags(&eBm, cudaEventDisableTiming);
    }

    // side chain: csr -> bma (linear on s1; never touches d_out)
    cudaEventRecord(eFork, 0);
    cudaStreamWaitEvent(s1, eFork, 0);
    k_csr<<<Nn / 8, 256, 0, s1>>>(g);
    cudaEventRecord(eCsr, s1);
    k_bma<<<Nn, 256, 0, s1>>>();
    cudaEventRecord(eBm, s1);

    // main: h-chain
    k_colstats<<<64, 256>>>(h);
    k_colfin  <<<1, 256>>>(gamma);
    k_norm    <<<(Nn * Dd / 4) / 256, 256>>>(h, beta);

    // rowfeat needs CSR + HN; bma keeps running underneath rowfeat/topk
    cudaStreamWaitEvent(0, eCsr, 0);
    k_rowfeat <<<Nn, 256>>>(wproj, bproj);
    k_topk    <<<1, 1024>>>(sigma1, out_idx);

    // outputs need bitmaps
    cudaStreamWaitEvent(0, eBm, 0);
    k_gather  <<<Kk, 256>>>(out_newh);
    k_gnew    <<<(Kk * Kk) / 256, 256>>>(out_gnew);
}

// round 16
// speedup vs baseline: 1.2849x; 1.0412x over previous
#include <cuda_runtime.h>
#include <cuda_fp16.h>
#include <math.h>

#define Nn 4096
#define Dd 256
#define Kk 2048
#define MAXD 128
#define EPSc 1e-5f

// ---------------- scratch (device globals; no allocation) ----------------
__device__ float  d_HN[Nn * Dd];        // normalized h (fp32, score path)
__device__ __half d_HNh[Nn * Dd];       // fp16 mirror (gather path only)
__device__ float  d_psum[64 * Dd];
__device__ float  d_psq[64 * Dd];
__device__ float  d_mu[Dd];
__device__ float  d_inv[Dd];
__device__ int    d_nbr[Nn * MAXD];
__device__ int    d_ncnt[Nn];
__device__ float  d_deg[Nn];
__device__ float  d_Z1[Nn];
__device__ float  d_Z3[Nn];
__device__ float  d_PF[Nn];
__device__ float  d_SC[Nn];
__device__ int    d_idx[Kk];
__device__ unsigned d_selw[Nn / 32];
__device__ unsigned d_bm[Kk * (Nn / 32)];   // per-selected-row two-hop bitmaps (1 MB)
__device__ float  d_rinv[Kk];

// ---------------- K1: column stats (deterministic 2-stage) ----------------
__global__ void k_colstats(const float* __restrict__ h) {
    int b = blockIdx.x, d = threadIdx.x;
    float s = 0.f, q = 0.f;
    int r0 = b * 64;
    for (int r = 0; r < 64; r++) {
        float v = h[(r0 + r) * Dd + d];
        s += v; q += v * v;
    }
    d_psum[b * Dd + d] = s;
    d_psq [b * Dd + d] = q;
}

// 1024 threads: 4 threads per column, each sums 16 partials; cross-part reduce in smem.
__global__ void k_colfin(const float* __restrict__ gamma) {
    __shared__ float ss[4][Dd];
    __shared__ float sq[4][Dd];
    int t = threadIdx.x;
    int d = t & (Dd - 1);
    int part = t >> 8;                  // 0..3
    float s = 0.f, q = 0.f;
    int b0 = part * 16;
    #pragma unroll
    for (int b = 0; b < 16; b++) {
        s += d_psum[(b0 + b) * Dd + d];
        q += d_psq [(b0 + b) * Dd + d];
    }
    ss[part][d] = s;
    sq[part][d] = q;
    __syncthreads();
    if (part == 0) {
        float S = ss[0][d] + ss[1][d] + ss[2][d] + ss[3][d];
        float Q = sq[0][d] + sq[1][d] + sq[2][d] + sq[3][d];
        float mu  = S / (float)Nn;
        float var = Q / (float)Nn - mu * mu;
        d_mu[d]  = mu;
        d_inv[d] = gamma[d] / sqrtf(var + EPSc);
    }
}

// ---------------- K2: normalize h (float4), fp32 + fp16 mirror ----------------
__global__ void k_norm(const float* __restrict__ h, const float* __restrict__ beta) {
    int t = blockIdx.x * blockDim.x + threadIdx.x;
    int d4 = t & (Dd / 4 - 1);
    float4 hv = ((const float4*)h)[t];
    float4 mu = ((const float4*)d_mu)[d4];
    float4 iv = ((const float4*)d_inv)[d4];
    float4 be = ((const float4*)beta)[d4];
    float4 o;
    o.x = (hv.x - mu.x) * iv.x + be.x;
    o.y = (hv.y - mu.y) * iv.y + be.y;
    o.z = (hv.z - mu.z) * iv.z + be.z;
    o.w = (hv.w - mu.w) * iv.w + be.w;
    ((float4*)d_HN)[t] = o;
    __half2 p0 = __floats2half2_rn(o.x, o.y);
    __half2 p1 = __floats2half2_rn(o.z, o.w);
    ((__half2*)d_HNh)[t * 2 + 0] = p0;
    ((__half2*)d_HNh)[t * 2 + 1] = p1;
}

// ---------------- K3: CSR from dense binary g ----------------
__global__ void k_csr(const float* __restrict__ g) {
    int row  = (blockIdx.x * blockDim.x + threadIdx.x) >> 5;
    int lane = threadIdx.x & 31;
    if (row >= Nn) return;
    const float4* r4 = (const float4*)(g + (size_t)row * Nn);
    int cnt = 0;
    for (int b = 0; b < 8; b++) {
        float4 v0 = r4[(b * 4 + 0) * 32 + lane];
        float4 v1 = r4[(b * 4 + 1) * 32 + lane];
        float4 v2 = r4[(b * 4 + 2) * 32 + lane];
        float4 v3 = r4[(b * 4 + 3) * 32 + lane];
        unsigned msk = 0u;
        msk |= (v0.x != 0.f) ? 0x0001u : 0u;  msk |= (v0.y != 0.f) ? 0x0002u : 0u;
        msk |= (v0.z != 0.f) ? 0x0004u : 0u;  msk |= (v0.w != 0.f) ? 0x0008u : 0u;
        msk |= (v1.x != 0.f) ? 0x0010u : 0u;  msk |= (v1.y != 0.f) ? 0x0020u : 0u;
        msk |= (v1.z != 0.f) ? 0x0040u : 0u;  msk |= (v1.w != 0.f) ? 0x0080u : 0u;
        msk |= (v2.x != 0.f) ? 0x0100u : 0u;  msk |= (v2.y != 0.f) ? 0x0200u : 0u;
        msk |= (v2.z != 0.f) ? 0x0400u : 0u;  msk |= (v2.w != 0.f) ? 0x0800u : 0u;
        msk |= (v3.x != 0.f) ? 0x1000u : 0u;  msk |= (v3.y != 0.f) ? 0x2000u : 0u;
        msk |= (v3.z != 0.f) ? 0x4000u : 0u;  msk |= (v3.w != 0.f) ? 0x8000u : 0u;
        int lc = __popc(msk);
        int inc = lc;
        #pragma unroll
        for (int o = 1; o < 32; o <<= 1) {
            int n = __shfl_up_sync(0xffffffffu, inc, o);
            if (lane >= o) inc += n;
        }
        int total = __shfl_sync(0xffffffffu, inc, 31);
        int base = cnt + inc - lc;
        while (msk) {
            int q = __ffs((int)msk) - 1;
            msk &= msk - 1;
            int col = (b * 4 + (q >> 2)) * 128 + lane * 4 + (q & 3);
            if (base < MAXD) d_nbr[row * MAXD + base] = col;
            base++;
        }
        cnt += total;
    }
    if (lane == 0) {
        d_ncnt[row] = cnt < MAXD ? cnt : MAXD;
        d_deg[row]  = (float)cnt;
    }
}

// ---------------- K4: per-row agg, Z1, Z3, pf ----------------
__global__ void k_rowfeat(const float* __restrict__ wproj, const float* __restrict__ bproj) {
    int i = blockIdx.x, d = threadIdx.x;
    __shared__ int   snb[MAXD];
    __shared__ float wr[8][3];
    int cnt = d_ncnt[i];
    if (d < cnt) snb[d] = d_nbr[i * MAXD + d];
    __syncthreads();
    float acc = 0.f;
    for (int e = 0; e < cnt; e++) acc += d_HN[snb[e] * Dd + d];
    float agg = acc / d_deg[i];
    float hv  = d_HN[i * Dd + d];
    float w   = wproj[d];
    float a = fabsf(hv - agg), b = agg * w, c = hv * w;
    for (int o = 16; o; o >>= 1) {
        a += __shfl_down_sync(0xffffffffu, a, o);
        b += __shfl_down_sync(0xffffffffu, b, o);
        c += __shfl_down_sync(0xffffffffu, c, o);
    }
    if ((d & 31) == 0) { wr[d >> 5][0] = a; wr[d >> 5][1] = b; wr[d >> 5][2] = c; }
    __syncthreads();
    if (d == 0) {
        float A = 0.f, B = 0.f, C = 0.f;
        for (int k = 0; k < 8; k++) { A += wr[k][0]; B += wr[k][1]; C += wr[k][2]; }
        float bb = bproj[0];
        d_Z1[i] = A;
        d_Z3[i] = B + bb;
        d_PF[i] = 1.f / (1.f + expf(-(C + bb)));
    }
}

// ---------------- K5: fused softmax + scores + top-k bitonic ----------------
__global__ void k_topk(const float* __restrict__ sigma1, float* __restrict__ out_idx) {
    __shared__ unsigned long long sk[Nn];
    __shared__ float sh[1024];
    int t = threadIdx.x;

    float mx = -3.4e38f;
    for (int i = t; i < Nn; i += 1024) mx = fmaxf(mx, d_Z3[i]);
    sh[t] = mx; __syncthreads();
    for (int s = 512; s > 0; s >>= 1) { if (t < s) sh[t] = fmaxf(sh[t], sh[t + s]); __syncthreads(); }
    float M = sh[0]; __syncthreads();
    float sm = 0.f;
    for (int i = t; i < Nn; i += 1024) sm += expf(d_Z3[i] - M);
    sh[t] = sm; __syncthreads();
    for (int s = 512; s > 0; s >>= 1) { if (t < s) sh[t] += sh[t + s]; __syncthreads(); }
    float S = sh[0];
    float s1 = sigma1[0];

    for (int i = t; i < Nn; i += 1024) {
        float pg = expf(d_Z3[i] - M) / S;
        float pl = 1.f / (1.f + expf(-(d_Z1[i] + d_deg[i])));
        float pt = 1.f / (1.f + expf(-(pl + pg)));
        float sc = s1 * pt + (1.f - s1) * d_PF[i];
        d_SC[i] = sc;
        unsigned u = __float_as_uint(sc);
        u = (u & 0x80000000u) ? ~u : (u | 0x80000000u);
        sk[i] = ((unsigned long long)(~u) << 32) | (unsigned)i;
    }
    if (t < Nn / 32) d_selw[t] = 0u;
    __syncthreads();

    for (int k = 2; k <= Nn; k <<= 1) {
        for (int j = k >> 1; j > 0; j >>= 1) {
            #pragma unroll
            for (int p = 0; p < 4; p++) {
                int i = t + p * 1024;
                int ixj = i ^ j;
                if (ixj > i) {
                    bool up = ((i & k) == 0);
                    unsigned long long a = sk[i], b = sk[ixj];
                    if ((a > b) == up) { sk[i] = b; sk[ixj] = a; }
                }
            }
            if (j >= 32) __syncthreads(); else __syncwarp();
        }
    }
    __syncthreads();
    for (int c = t; c < Kk; c += 1024) {
        int j = (int)(sk[c] & 0xffffffffULL);
        d_idx[c] = j;
        atomicOr(&d_selw[j >> 5], 1u << (j & 31));
        out_idx[c] = (float)j;
    }
}

// ---------------- K6: per-selected-row two-hop -> new_h (fp16 gather), bitmap, rinv -----
__global__ void k_pool(float* __restrict__ out_newh) {
    __shared__ unsigned bm[Nn / 32];
    __shared__ int scn[Nn / 32];
    __shared__ int list[Nn];
    __shared__ float red[7][32][8];
    __shared__ int redi[256];
    int r = blockIdx.x, d = threadIdx.x;
    int i = d_idx[r];
    if (d < Nn / 32) bm[d] = 0u;
    __syncthreads();

    // two-hop expansion into bitmap
    int c1 = d_ncnt[i];
    for (int e = d; e < c1; e += 256) {
        int k = d_nbr[i * MAXD + e];
        int c2 = d_ncnt[k];
        const int* nb = &d_nbr[k * MAXD];
        for (int f = 0; f < c2; f++) {
            int j = nb[f];
            atomicOr(&bm[j >> 5], 1u << (j & 31));
        }
    }
    __syncthreads();

    // deterministic ordered extraction via prefix scan over 128 words
    int pc = (d < Nn / 32) ? __popc(bm[d]) : 0;
    if (d < Nn / 32) scn[d] = pc;
    __syncthreads();
    for (int off = 1; off < Nn / 32; off <<= 1) {
        int v = 0;
        if (d < Nn / 32) { v = scn[d]; if (d >= off) v += scn[d - off]; }
        __syncthreads();
        if (d < Nn / 32) scn[d] = v;
        __syncthreads();
    }
    if (d < Nn / 32) {
        int p = scn[d] - pc;
        unsigned v = bm[d];
        while (v) { int b = __ffs((int)v) - 1; v &= v - 1; list[p++] = d * 32 + b; }
        d_bm[r * (Nn / 32) + d] = bm[d];
    }
    int csel = (d < Nn / 32) ? __popc(bm[d] & d_selw[d]) : 0;
    redi[d] = csel;
    __syncthreads();
    int m = scn[Nn / 32 - 1];
    for (int s = 128; s > 0; s >>= 1) { if (d < s) redi[d] += redi[d + s]; __syncthreads(); }
    if (d == 0) d_rinv[r] = 1.f / (float)redi[0];

    // fp16 gather: 8 groups x 32 lanes, 8 dims/lane, unroll-4
    int grp = d >> 5, l = d & 31;
    const uint4* H4 = (const uint4*)d_HNh;
    float acc0[8], acc1[8];
    #pragma unroll
    for (int q = 0; q < 8; q++) { acc0[q] = 0.f; acc1[q] = 0.f; }
    int e = grp;
    for (; e + 24 < m; e += 32) {
        int j0 = list[e], j1 = list[e + 8], j2 = list[e + 16], j3 = list[e + 24];
        float s0 = d_SC[j0], s1 = d_SC[j1], s2 = d_SC[j2], s3 = d_SC[j3];
        uint4 va = H4[j0 * 32 + l];
        uint4 vb = H4[j1 * 32 + l];
        uint4 vc = H4[j2 * 32 + l];
        uint4 vd = H4[j3 * 32 + l];
        const __half2* ha = (const __half2*)&va;
        const __half2* hb = (const __half2*)&vb;
        const __half2* hc = (const __half2*)&vc;
        const __half2* hd = (const __half2*)&vd;
        #pragma unroll
        for (int q = 0; q < 4; q++) {
            float2 fa = __half22float2(ha[q]);
            float2 fb = __half22float2(hb[q]);
            float2 fc = __half22float2(hc[q]);
            float2 fd = __half22float2(hd[q]);
            acc0[q * 2 + 0] += s0 * fa.x + s2 * fc.x;
            acc0[q * 2 + 1] += s0 * fa.y + s2 * fc.y;
            acc1[q * 2 + 0] += s1 * fb.x + s3 * fd.x;
            acc1[q * 2 + 1] += s1 * fb.y + s3 * fd.y;
        }
    }
    for (; e < m; e += 8) {
        int j = list[e];
        float s = d_SC[j];
        uint4 v = H4[j * 32 + l];
        const __half2* hp = (const __half2*)&v;
        #pragma unroll
        for (int q = 0; q < 4; q++) {
            float2 f = __half22float2(hp[q]);
            acc0[q * 2 + 0] += s * f.x; acc0[q * 2 + 1] += s * f.y;
        }
    }
    #pragma unroll
    for (int q = 0; q < 8; q++) acc0[q] += acc1[q];
    if (grp > 0) {
        #pragma unroll
        for (int q = 0; q < 8; q++) red[grp - 1][l][q] = acc0[q];
    }
    __syncthreads();
    if (grp == 0) {
        #pragma unroll
        for (int gq = 0; gq < 7; gq++)
            #pragma unroll
            for (int q = 0; q < 8; q++) acc0[q] += red[gq][l][q];
        float4 o0 = make_float4(acc0[0], acc0[1], acc0[2], acc0[3]);
        float4 o1 = make_float4(acc0[4], acc0[5], acc0[6], acc0[7]);
        ((float4*)out_newh)[(size_t)r * 64 + l * 2 + 0] = o0;
        ((float4*)out_newh)[(size_t)r * 64 + l * 2 + 1] = o1;
    }
}

// ---------------- K7: write g_new (membership bit * column rinv) ----------------
__global__ void k_gnew(float* __restrict__ out_gnew) {
    int t = blockIdx.x * blockDim.x + threadIdx.x;
    int r = t >> 11, c = t & (Kk - 1);
    int j = d_idx[c];
    unsigned w = d_bm[r * (Nn / 32) + (j >> 5)];
    out_gnew[t] = ((w >> (j & 31)) & 1u) ? d_rinv[c] : 0.f;
}

// ---------------- launch (fork csr onto side stream; join before rowfeat) ----------------
extern "C" void kernel_launch(void* const* d_in, const int* in_sizes, int n_in,
                              void* d_out, int out_size) {
    const float* g      = (const float*)d_in[0];
    const float* h      = (const float*)d_in[1];
    const float* gamma  = (const float*)d_in[2];
    const float* beta   = (const float*)d_in[3];
    const float* wproj  = (const float*)d_in[4];
    const float* bproj  = (const float*)d_in[5];
    const float* sigma1 = (const float*)d_in[6];

    float* out      = (float*)d_out;
    float* out_gnew = out;                               // Kk*Kk
    float* out_newh = out + (size_t)Kk * Kk;             // Kk*Dd
    float* out_idx  = out_newh + (size_t)Kk * Dd;        // Kk

    static cudaStream_t s1 = nullptr;
    static cudaEvent_t  eFork = nullptr, eJoin = nullptr;
    if (s1 == nullptr) {
        cudaStreamCreateWithFlags(&s1, cudaStreamNonBlocking);
        cudaEventCreateWithFlags(&eFork, cudaEventDisableTiming);
        cudaEventCreateWithFlags(&eJoin, cudaEventDisableTiming);
    }

    cudaEventRecord(eFork, 0);
    cudaStreamWaitEvent(s1, eFork, 0);
    k_csr<<<Nn / 8, 256, 0, s1>>>(g);
    cudaEventRecord(eJoin, s1);

    k_colstats<<<64, 256>>>(h);
    k_colfin  <<<1, 1024>>>(gamma);
    k_norm    <<<(Nn * Dd / 4) / 256, 256>>>(h, beta);

    cudaStreamWaitEvent(0, eJoin, 0);
    k_rowfeat <<<Nn, 256>>>(wproj, bproj);
    k_topk    <<<1, 1024>>>(sigma1, out_idx);
    k_pool    <<<Kk, 256>>>(out_newh);
    k_gnew    <<<(Kk * Kk) / 256, 256>>>(out_gnew);
}